// round 2
// baseline (speedup 1.0000x reference)
#include <cuda_runtime.h>
#include <cuda_bf16.h>

// SEIR RNN: 65536 independent 4-state trajectories, 200 Euler steps, all
// states written out (210 MB) => HBM-store-bound, but grid-limited to
// ~14 warps/SM, so intra-warp serialization must be minimal.
//
// R1 -> R2 changes:
//  * warp-private smem tiles + __syncwarp (no block barriers)
//  * clamp dropped (provably inactive: states bounded by conserved sum
//    ~4000 << 1e5 clamp; all Euler factors in (0,1])
//  * algebra folded to 8 FMA-class ops/step (precomputed H*B/N, 1-H*A, ...)

#define BATCH   65536
#define STEPS   200
#define CHUNK   8
#define NCHUNK  (STEPS / CHUNK)   // 25
#define TPB     128
#define WARPS   (TPB / 32)

__global__ __launch_bounds__(TPB, 8)
void seir_kernel(const float4* __restrict__ init,
                 const float*  __restrict__ w,
                 float4*       __restrict__ out)
{
    // Warp-private tile: [lane][step], +1 float4 row pad -> stride 144 B,
    // conflict-free for both the per-step STS and the transposed LDS drain.
    __shared__ float4 buf[WARPS][32][CHUNK + 1];

    const int tid  = threadIdx.x;
    const int wrp  = tid >> 5;
    const int lane = tid & 31;
    const int bw   = blockIdx.x * TPB + wrp * 32;   // first trajectory of warp
    const int b    = bw + lane;                     // this thread's trajectory

    const float A = w[4];
    const float B = w[5];
    const float C = w[6];
    const float H = 0.5f;
    const float kB = H * B * 1e-5f;   // H*B/N_POP
    const float cA = 1.0f - H * A;
    const float cC = 1.0f - H * C;
    const float kA = H * A;
    const float kC = H * C;

    float4 x = init[b];
    float s = x.x, e = x.y, i = x.z, r = x.w;

    // precomputed drain indices (lane-constant)
    const int bl = lane >> 3;         // 0..3 : trajectory sub-index per k
    const int t  = lane & 7;          // 0..7 : step within chunk
    float4* const out_base = out + (size_t)(bw) * STEPS + t;

    for (int c = 0; c < NCHUNK; ++c) {
        // ---- compute 8 steps, stage in warp-private shared tile ----
        #pragma unroll
        for (int tt = 0; tt < CHUNK; ++tt) {
            float p     = e + i;
            float inflH = kB * p * s;
            float eo = e, io = i;
            s = s - inflH;
            e = fmaf(cA, eo, inflH);
            i = fmaf(cC, io, kA * eo);
            r = fmaf(kC, io, r);
            buf[wrp][lane][tt] = make_float4(s, e, i, r);
        }
        __syncwarp();

        // ---- coalesced drain: per k, lanes cover trajs 4k..4k+3, steps 0..7
        //      (8 lanes = one full 128 B line of one trajectory) ----
        const int tbase = c * CHUNK;
        #pragma unroll
        for (int k = 0; k < CHUNK; ++k) {
            int bl_k = 4 * k + bl;
            out_base[(size_t)bl_k * STEPS + tbase] = buf[wrp][bl_k][t];
        }
        __syncwarp();   // protect tile reuse next chunk
    }
}

extern "C" void kernel_launch(void* const* d_in, const int* in_sizes, int n_in,
                              void* d_out, int out_size)
{
    const float4* init = (const float4*)d_in[0];   // (65536,1,4) f32
    const float*  wts  = (const float*)d_in[1];    // (7,) f32
    float4*       out  = (float4*)d_out;           // (65536,200,1,4) f32

    seir_kernel<<<BATCH / TPB, TPB>>>(init, wts, out);
}

// round 3
// speedup vs baseline: 1.0131x; 1.0131x over previous
#include <cuda_runtime.h>
#include <cuda_bf16.h>

// SEIR RNN: 65536 independent 4-state trajectories, 200 Euler steps, all
// states written out (210 MB) => bound by the L2->DRAM write path.
//
// R2 -> R3 changes:
//  * __stcs (evict-first streaming) on output stores: output is write-once,
//    never re-read; start L2 writeback immediately instead of lazy bursts.
//  * double-buffered warp-private smem tile -> one __syncwarp per chunk.

#define BATCH   65536
#define STEPS   200
#define CHUNK   8
#define NCHUNK  (STEPS / CHUNK)   // 25
#define TPB     128
#define WARPS   (TPB / 32)

__global__ __launch_bounds__(TPB, 8)
void seir_kernel(const float4* __restrict__ init,
                 const float*  __restrict__ w,
                 float4*       __restrict__ out)
{
    // Double-buffered warp-private tile: [buf][warp][lane][step], +1 float4
    // row pad -> stride 144 B, conflict-free for STS and transposed LDS.
    __shared__ float4 buf[2][WARPS][32][CHUNK + 1];

    const int tid  = threadIdx.x;
    const int wrp  = tid >> 5;
    const int lane = tid & 31;
    const int bw   = blockIdx.x * TPB + wrp * 32;   // first trajectory of warp
    const int b    = bw + lane;                     // this thread's trajectory

    const float A = w[4];
    const float B = w[5];
    const float C = w[6];
    const float H = 0.5f;
    const float kB = H * B * 1e-5f;   // H*B/N_POP
    const float cA = 1.0f - H * A;
    const float cC = 1.0f - H * C;
    const float kA = H * A;
    const float kC = H * C;

    float4 x = init[b];
    float s = x.x, e = x.y, i = x.z, r = x.w;

    // lane-constant drain indices
    const int bl = lane >> 3;         // 0..3 : trajectory sub-index per k
    const int t  = lane & 7;          // 0..7 : step within chunk
    float4* const out_base = out + (size_t)(bw) * STEPS + t;

    for (int c = 0; c < NCHUNK; ++c) {
        const int pb = c & 1;
        // ---- compute 8 steps, stage in warp-private shared tile ----
        #pragma unroll
        for (int tt = 0; tt < CHUNK; ++tt) {
            float p     = e + i;
            float inflH = kB * p * s;
            float eo = e, io = i;
            s = s - inflH;
            e = fmaf(cA, eo, inflH);
            i = fmaf(cC, io, kA * eo);
            r = fmaf(kC, io, r);
            buf[pb][wrp][lane][tt] = make_float4(s, e, i, r);
        }
        __syncwarp();

        // ---- coalesced streaming drain: per k, 8 lanes cover one full
        //      128 B line (one trajectory x 8 steps); evict-first policy ----
        const int tbase = c * CHUNK;
        #pragma unroll
        for (int k = 0; k < CHUNK; ++k) {
            int bl_k = 4 * k + bl;
            __stcs(&out_base[(size_t)bl_k * STEPS + tbase],
                   buf[pb][wrp][bl_k][t]);
        }
        // no trailing sync: next chunk writes the other buffer
    }
}

extern "C" void kernel_launch(void* const* d_in, const int* in_sizes, int n_in,
                              void* d_out, int out_size)
{
    const float4* init = (const float4*)d_in[0];   // (65536,1,4) f32
    const float*  wts  = (const float*)d_in[1];    // (7,) f32
    float4*       out  = (float4*)d_out;           // (65536,200,1,4) f32

    seir_kernel<<<BATCH / TPB, TPB>>>(init, wts, out);
}